// round 3
// baseline (speedup 1.0000x reference)
#include <cuda_runtime.h>
#include <cstdint>

// Problem shape (fixed by dataset)
#define N_MAX   50000
#define E_MAX   800000
#define EMB     128
#define KTOT    256     // NF + EMB

// ---------------- device scratch (static: no runtime allocation) -----------
__device__ int    g_deg[N_MAX];
__device__ int    g_off[N_MAX + 1];
__device__ int    g_cur[N_MAX];
__device__ int    g_eidx[E_MAX];
__device__ float4 g_aggr4[N_MAX * (EMB / 4)];   // [N][32] float4 = h_aggr

// ---------------- 1) zero degree counters ----------------------------------
__global__ void zero_deg_kernel(int n) {
    int i = blockIdx.x * blockDim.x + threadIdx.x;
    if (i < n) g_deg[i] = 0;
}

// ---------------- 2) histogram of edge destinations -------------------------
__global__ void hist_kernel(const int* __restrict__ dst, int e) {
    int i = blockIdx.x * blockDim.x + threadIdx.x;
    if (i < e) atomicAdd(&g_deg[dst[i]], 1);
}

// ---------------- 3) exclusive prefix scan (single CTA, 1024 threads) ------
__global__ void scan_kernel(int n) {
    const int T = 1024;
    int tid  = threadIdx.x;
    int lane = tid & 31;
    int wid  = tid >> 5;
    int C = (n + T - 1) / T;
    int s = tid * C;
    int e = min(s + C, n);

    int sum = 0;
    for (int i = s; i < e; i++) sum += g_deg[i];

    // block-wide exclusive scan of per-thread sums
    int v = sum;
    #pragma unroll
    for (int d = 1; d < 32; d <<= 1) {
        int t = __shfl_up_sync(0xffffffffu, v, d);
        if (lane >= d) v += t;
    }
    __shared__ int wsum[32];
    if (lane == 31) wsum[wid] = v;
    __syncthreads();
    if (wid == 0) {
        int w = wsum[lane];
        #pragma unroll
        for (int d = 1; d < 32; d <<= 1) {
            int t = __shfl_up_sync(0xffffffffu, w, d);
            if (lane >= d) w += t;
        }
        wsum[lane] = w;   // inclusive across warps
    }
    __syncthreads();

    int excl = (v - sum) + (wid > 0 ? wsum[wid - 1] : 0);

    int run = excl;
    for (int i = s; i < e; i++) {
        g_off[i] = run;
        g_cur[i] = run;
        run += g_deg[i];
    }
    if (e == n) g_off[n] = run;   // all such threads write the same total
}

// ---------------- 4) scatter edge ids into CSR ------------------------------
__global__ void scatter_kernel(const int* __restrict__ dst, int e) {
    int i = blockIdx.x * blockDim.x + threadIdx.x;
    if (i < e) {
        int d = dst[i];
        int pos = atomicAdd(&g_cur[d], 1);
        g_eidx[pos] = i;
    }
}

// ---------------- 5) gather: h_aggr[n] = sum_{e: dst(e)=n} h[e] -------------
// One warp per node, one float4 per lane -> full 512B row per warp per edge.
__global__ void gather_kernel(const float4* __restrict__ h4, int n) {
    int gw   = (blockIdx.x * blockDim.x + threadIdx.x) >> 5;
    int lane = threadIdx.x & 31;
    if (gw >= n) return;
    int s = g_off[gw];
    int e = g_off[gw + 1];
    float4 a = make_float4(0.f, 0.f, 0.f, 0.f);
    int j = s;
    for (; j + 2 <= e; j += 2) {            // unroll 2 for MLP
        int e0 = g_eidx[j];
        int e1 = g_eidx[j + 1];
        float4 v0 = __ldg(&h4[(size_t)e0 * 32 + lane]);
        float4 v1 = __ldg(&h4[(size_t)e1 * 32 + lane]);
        a.x += v0.x + v1.x;
        a.y += v0.y + v1.y;
        a.z += v0.z + v1.z;
        a.w += v0.w + v1.w;
    }
    if (j < e) {
        int e0 = g_eidx[j];
        float4 v0 = __ldg(&h4[(size_t)e0 * 32 + lane]);
        a.x += v0.x; a.y += v0.y; a.z += v0.z; a.w += v0.w;
    }
    g_aggr4[(size_t)gw * 32 + lane] = a;
}

// ---------------- 6) fused GEMM + bias + ReLU --------------------------------
// out[n, c] = relu( sum_k q[n,k] * W[c,k] + b[c] ),  q = concat(x, h_aggr)
// Tile: BM=64 nodes x BN=128 cols x BK=32, 256 threads, 4x8 register tile,
// inner product via packed fma.rn.f32x2 (2 cols per instruction).
#define BM 64
#define BK 32
#define BN 128
#define QS (BM + 4)   // padded stride for sQ to tame bank conflicts

__device__ __forceinline__ void ffma2(unsigned long long& d,
                                      unsigned long long a,
                                      unsigned long long b) {
    asm("fma.rn.f32x2 %0, %1, %2, %0;" : "+l"(d) : "l"(a), "l"(b));
}

__global__ void __launch_bounds__(256)
gemm_relu_kernel(const float* __restrict__ x,
                 const float* __restrict__ W,
                 const float* __restrict__ bias,
                 float* __restrict__ out, int n) {
    __shared__ float sW[BK * BN];   // [k][c]
    __shared__ float sQ[BK * QS];   // [k][m], padded

    const float* aggr = reinterpret_cast<const float*>(g_aggr4);

    int tid = threadIdx.x;
    int tm  = tid & 15;        // node group
    int tn  = tid >> 4;        // col group
    int m0  = tm * 4;
    int c0  = tn * 8;
    int nb  = blockIdx.x * BM;

    unsigned long long acc[4][4];
    #pragma unroll
    for (int i = 0; i < 4; i++)
        #pragma unroll
        for (int p = 0; p < 4; p++)
            acc[i][p] = 0ULL;   // packed (0.f, 0.f)

    for (int kc = 0; kc < KTOT; kc += BK) {
        // stage W chunk: sW[k][c] = W[c*KTOT + kc + k]
        #pragma unroll
        for (int f = tid; f < BK * BN / 4; f += 256) {   // 1024 float4
            int c  = f >> 3;
            int kq = f & 7;
            float4 w = *reinterpret_cast<const float4*>(W + (size_t)c * KTOT + kc + kq * 4);
            sW[(kq * 4 + 0) * BN + c] = w.x;
            sW[(kq * 4 + 1) * BN + c] = w.y;
            sW[(kq * 4 + 2) * BN + c] = w.z;
            sW[(kq * 4 + 3) * BN + c] = w.w;
        }
        // stage Q chunk: sQ[k][m] = q[nb+m][kc+k]
        const float* src = (kc < 128) ? (x + kc) : (aggr + (kc - 128));
        #pragma unroll
        for (int f = tid; f < BK * BM / 4; f += 256) {   // 512 float4
            int m  = f >> 3;
            int kq = f & 7;
            int node = nb + m;
            float4 v = make_float4(0.f, 0.f, 0.f, 0.f);
            if (node < n)
                v = *reinterpret_cast<const float4*>(src + (size_t)node * 128 + kq * 4);
            sQ[(kq * 4 + 0) * QS + m] = v.x;
            sQ[(kq * 4 + 1) * QS + m] = v.y;
            sQ[(kq * 4 + 2) * QS + m] = v.z;
            sQ[(kq * 4 + 3) * QS + m] = v.w;
        }
        __syncthreads();

        #pragma unroll
        for (int k = 0; k < BK; k++) {
            float4 w0 = *reinterpret_cast<const float4*>(sW + k * BN + c0);
            float4 w1 = *reinterpret_cast<const float4*>(sW + k * BN + c0 + 4);
            unsigned long long wp[4];
            const unsigned long long* u0 = reinterpret_cast<const unsigned long long*>(&w0);
            const unsigned long long* u1 = reinterpret_cast<const unsigned long long*>(&w1);
            wp[0] = u0[0]; wp[1] = u0[1]; wp[2] = u1[0]; wp[3] = u1[1];

            #pragma unroll
            for (int i = 0; i < 4; i++) {
                float q = sQ[k * QS + m0 + i];
                unsigned long long qq;
                asm("mov.b64 %0, {%1, %1};" : "=l"(qq) : "r"(__float_as_uint(q)));
                ffma2(acc[i][0], wp[0], qq);
                ffma2(acc[i][1], wp[1], qq);
                ffma2(acc[i][2], wp[2], qq);
                ffma2(acc[i][3], wp[3], qq);
            }
        }
        __syncthreads();
    }

    // epilogue: bias + relu + store
    const float2* b2 = reinterpret_cast<const float2*>(bias);
    float2 bb[4];
    #pragma unroll
    for (int p = 0; p < 4; p++) bb[p] = b2[(c0 >> 1) + p];

    #pragma unroll
    for (int i = 0; i < 4; i++) {
        int node = nb + m0 + i;
        if (node >= n) continue;
        float o[8];
        #pragma unroll
        for (int p = 0; p < 4; p++) {
            unsigned int lo, hi;
            asm("mov.b64 {%0, %1}, %2;" : "=r"(lo), "=r"(hi) : "l"(acc[i][p]));
            float fl = __uint_as_float(lo) + bb[p].x;
            float fh = __uint_as_float(hi) + bb[p].y;
            o[2 * p + 0] = fmaxf(fl, 0.f);
            o[2 * p + 1] = fmaxf(fh, 0.f);
        }
        float4 v0 = make_float4(o[0], o[1], o[2], o[3]);
        float4 v1 = make_float4(o[4], o[5], o[6], o[7]);
        *reinterpret_cast<float4*>(out + (size_t)node * EMB + c0)     = v0;
        *reinterpret_cast<float4*>(out + (size_t)node * EMB + c0 + 4) = v1;
    }
}

// ---------------- launch ----------------------------------------------------
extern "C" void kernel_launch(void* const* d_in, const int* in_sizes, int n_in,
                              void* d_out, int out_size) {
    const float* h        = (const float*)d_in[0];   // [E, 128]
    const float* x        = (const float*)d_in[1];   // [N, 128]
    const int*   edge_dst = (const int*)  d_in[2];   // [E] int32
    const float* W        = (const float*)d_in[3];   // [128, 256]
    const float* b        = (const float*)d_in[4];   // [128]
    float*       out      = (float*)d_out;           // [N, 128]

    int E = in_sizes[2];
    int N = in_sizes[1] / EMB;

    zero_deg_kernel<<<(N + 255) / 256, 256>>>(N);
    hist_kernel<<<(E + 255) / 256, 256>>>(edge_dst, E);
    scan_kernel<<<1, 1024>>>(N);
    scatter_kernel<<<(E + 255) / 256, 256>>>(edge_dst, E);
    gather_kernel<<<(N * 32 + 255) / 256, 256>>>(
        reinterpret_cast<const float4*>(h), N);
    gemm_relu_kernel<<<(N + BM - 1) / BM, 256>>>(x, W, b, out, N);
}

// round 4
// speedup vs baseline: 1.0389x; 1.0389x over previous
#include <cuda_runtime.h>
#include <cstdint>

// Problem shape (fixed by dataset)
#define N_MAX   50000
#define E_MAX   800000
#define EMB     128
#define KTOT    256     // NF + EMB

// ---------------- device scratch (static: no runtime allocation) -----------
__device__ int g_deg[N_MAX];
__device__ int g_off[N_MAX + 1];
__device__ int g_rank[E_MAX];
__device__ int g_eidx[E_MAX];

// ---------------- 1) zero degree counters ----------------------------------
__global__ void zero_deg_kernel(int n) {
    int i = blockIdx.x * blockDim.x + threadIdx.x;
    if (i < n) g_deg[i] = 0;
}

// ---------------- 2) histogram + per-edge rank in one pass -------------------
__global__ void hist_rank_kernel(const int* __restrict__ dst, int e) {
    int i = blockIdx.x * blockDim.x + threadIdx.x;
    if (i < e) g_rank[i] = atomicAdd(&g_deg[dst[i]], 1);
}

// ---------------- 3) exclusive prefix scan (single CTA, 1024 threads) ------
__global__ void scan_kernel(int n) {
    const int T = 1024;
    int tid  = threadIdx.x;
    int lane = tid & 31;
    int wid  = tid >> 5;
    int C = (n + T - 1) / T;
    int s = tid * C;
    int e = min(s + C, n);

    int sum = 0;
    for (int i = s; i < e; i++) sum += g_deg[i];

    int v = sum;
    #pragma unroll
    for (int d = 1; d < 32; d <<= 1) {
        int t = __shfl_up_sync(0xffffffffu, v, d);
        if (lane >= d) v += t;
    }
    __shared__ int wsum[32];
    if (lane == 31) wsum[wid] = v;
    __syncthreads();
    if (wid == 0) {
        int w = wsum[lane];
        #pragma unroll
        for (int d = 1; d < 32; d <<= 1) {
            int t = __shfl_up_sync(0xffffffffu, w, d);
            if (lane >= d) w += t;
        }
        wsum[lane] = w;
    }
    __syncthreads();

    int excl = (v - sum) + (wid > 0 ? wsum[wid - 1] : 0);

    int run = excl;
    for (int i = s; i < e; i++) {
        g_off[i] = run;
        run += g_deg[i];
    }
    if (e == n) g_off[n] = run;
}

// ---------------- 4) scatter edge ids into CSR (no atomics) -----------------
__global__ void scatter_kernel(const int* __restrict__ dst, int e) {
    int i = blockIdx.x * blockDim.x + threadIdx.x;
    if (i < e) g_eidx[g_off[dst[i]] + g_rank[i]] = i;
}

// ---------------- 5) fused gather + concat + GEMM + bias + ReLU -------------
// One CTA handles BM=64 nodes. Phase A: load x rows into k-major swizzled sQ.
// Phase B: CSR gather of h rows into sQ rows 128..255. Phase C: GEMM with
// fma.rn.f32x2 packed along m (2 nodes per instruction).
//
// sQ layout: row k (256 rows) x 64 floats (m). Each row has 16 float4 slots;
// slot is XOR-swizzled: slot' = slot ^ ((k>>2) & 15). This makes both the
// strided per-lane scalar stores (gather/x phases) and the float4 reads
// (GEMM phase) shared-memory-bank friendly.
// sW layout: c-major [128][68] so GEMM reads W as LDS.128 along k.
#define BM   64
#define SWS  68                        // sW row stride (floats), mult of 4
#define SQ_WORDS (KTOT * 64)           // 16384 floats
#define SW_WORDS (EMB * SWS)           // 8704 floats
#define SMEM_BYTES ((SQ_WORDS + SW_WORDS) * 4)   // 100352 B

__device__ __forceinline__ void ffma2(unsigned long long& d,
                                      unsigned long long a,
                                      unsigned long long b) {
    asm("fma.rn.f32x2 %0, %1, %2, %0;" : "+l"(d) : "l"(a), "l"(b));
}

__device__ __forceinline__ unsigned long long dup2(float v) {
    unsigned long long r;
    asm("mov.b64 %0, {%1, %1};" : "=l"(r) : "r"(__float_as_uint(v)));
    return r;
}

__global__ void __launch_bounds__(256, 2)
fused_kernel(const float4* __restrict__ h4,
             const float4* __restrict__ x4,
             const float*  __restrict__ W,
             const float*  __restrict__ bias,
             float* __restrict__ out, int n) {
    extern __shared__ float smem[];
    float* sQ = smem;                  // [256][64] swizzled
    float* sW = smem + SQ_WORDS;       // [128][68] c-major

    int tid  = threadIdx.x;
    int warp = tid >> 5;
    int lane = tid & 31;
    int nb   = blockIdx.x * BM;

    // ---- Phase A: x rows -> sQ rows [0,128) ----
    #pragma unroll
    for (int f = tid; f < BM * 32; f += 256) {   // 2048 float4
        int m  = f >> 5;
        int kq = f & 31;
        int node = nb + m;
        float4 v = make_float4(0.f, 0.f, 0.f, 0.f);
        if (node < n) v = x4[(size_t)node * 32 + kq];
        int off = (((m >> 2) ^ (kq & 15)) << 2) + (m & 3);
        int row = 4 * kq;
        sQ[(row + 0) * 64 + off] = v.x;
        sQ[(row + 1) * 64 + off] = v.y;
        sQ[(row + 2) * 64 + off] = v.z;
        sQ[(row + 3) * 64 + off] = v.w;
    }

    // ---- Phase B: CSR gather -> sQ rows [128,256) ----
    for (int m = warp; m < BM; m += 8) {
        int node = nb + m;
        float4 a = make_float4(0.f, 0.f, 0.f, 0.f);
        if (node < n) {
            int s = g_off[node];
            int e = g_off[node + 1];
            int j = s;
            for (; j + 4 <= e; j += 4) {
                int e0 = __ldg(g_eidx + j + 0);
                int e1 = __ldg(g_eidx + j + 1);
                int e2 = __ldg(g_eidx + j + 2);
                int e3 = __ldg(g_eidx + j + 3);
                float4 v0 = __ldg(h4 + (size_t)e0 * 32 + lane);
                float4 v1 = __ldg(h4 + (size_t)e1 * 32 + lane);
                float4 v2 = __ldg(h4 + (size_t)e2 * 32 + lane);
                float4 v3 = __ldg(h4 + (size_t)e3 * 32 + lane);
                a.x += (v0.x + v1.x) + (v2.x + v3.x);
                a.y += (v0.y + v1.y) + (v2.y + v3.y);
                a.z += (v0.z + v1.z) + (v2.z + v3.z);
                a.w += (v0.w + v1.w) + (v2.w + v3.w);
            }
            for (; j < e; j++) {
                int e0 = __ldg(g_eidx + j);
                float4 v0 = __ldg(h4 + (size_t)e0 * 32 + lane);
                a.x += v0.x; a.y += v0.y; a.z += v0.z; a.w += v0.w;
            }
        }
        int off = (((m >> 2) ^ (lane & 15)) << 2) + (m & 3);
        int row = 128 + 4 * lane;
        sQ[(row + 0) * 64 + off] = a.x;
        sQ[(row + 1) * 64 + off] = a.y;
        sQ[(row + 2) * 64 + off] = a.z;
        sQ[(row + 3) * 64 + off] = a.w;
    }
    __syncthreads();

    // ---- Phase C: GEMM. tile 64m x 128c, per-thread 4m x 8c ----
    int tm = tid & 15;
    int tn = tid >> 4;
    int m0 = tm * 4;
    int c0 = tn * 8;

    unsigned long long acc[8][2];      // [col p][m-pair]
    #pragma unroll
    for (int p = 0; p < 8; p++) { acc[p][0] = 0ULL; acc[p][1] = 0ULL; }

    for (int kc = 0; kc < KTOT; kc += 64) {
        // stage sW[c][kk] for kk in [0,64): coalesced load, contiguous store
        #pragma unroll
        for (int f = tid; f < EMB * 16; f += 256) {   // 2048 float4
            int c  = f >> 4;
            int kq = f & 15;
            float4 w = *reinterpret_cast<const float4*>(W + (size_t)c * KTOT + kc + kq * 4);
            *reinterpret_cast<float4*>(sW + c * SWS + kq * 4) = w;
        }
        __syncthreads();

        #pragma unroll 4
        for (int k4 = 0; k4 < 16; k4++) {
            int kk = k4 * 4;
            int kg = kc + kk;
            int sw = (tm ^ ((kg >> 2) & 15)) << 2;

            // q[kg+j][m0..m0+3], one LDS.128 per k
            float4 q0 = *reinterpret_cast<const float4*>(sQ + (kg + 0) * 64 + sw);
            float4 q1 = *reinterpret_cast<const float4*>(sQ + (kg + 1) * 64 + sw);
            float4 q2 = *reinterpret_cast<const float4*>(sQ + (kg + 2) * 64 + sw);
            float4 q3 = *reinterpret_cast<const float4*>(sQ + (kg + 3) * 64 + sw);
            const unsigned long long* qp0 = reinterpret_cast<const unsigned long long*>(&q0);
            const unsigned long long* qp1 = reinterpret_cast<const unsigned long long*>(&q1);
            const unsigned long long* qp2 = reinterpret_cast<const unsigned long long*>(&q2);
            const unsigned long long* qp3 = reinterpret_cast<const unsigned long long*>(&q3);

            // W[c0+p][kk..kk+3], one LDS.128 per col
            float4 w4[8];
            #pragma unroll
            for (int p = 0; p < 8; p++)
                w4[p] = *reinterpret_cast<const float4*>(sW + (c0 + p) * SWS + kk);

            #pragma unroll
            for (int p = 0; p < 8; p++) {
                unsigned long long b0 = dup2(w4[p].x);
                ffma2(acc[p][0], qp0[0], b0);
                ffma2(acc[p][1], qp0[1], b0);
                unsigned long long b1 = dup2(w4[p].y);
                ffma2(acc[p][0], qp1[0], b1);
                ffma2(acc[p][1], qp1[1], b1);
                unsigned long long b2 = dup2(w4[p].z);
                ffma2(acc[p][0], qp2[0], b2);
                ffma2(acc[p][1], qp2[1], b2);
                unsigned long long b3 = dup2(w4[p].w);
                ffma2(acc[p][0], qp3[0], b3);
                ffma2(acc[p][1], qp3[1], b3);
            }
        }
        __syncthreads();
    }

    // ---- epilogue: bias + relu + store ----
    float4 ba = *reinterpret_cast<const float4*>(bias + c0);
    float4 bb = *reinterpret_cast<const float4*>(bias + c0 + 4);
    float bv[8] = {ba.x, ba.y, ba.z, ba.w, bb.x, bb.y, bb.z, bb.w};

    #pragma unroll
    for (int i = 0; i < 4; i++) {
        int node = nb + m0 + i;
        if (node >= n) continue;
        int pr = i >> 1;      // m-pair index
        int hf = i & 1;       // lo/hi within pair
        float o[8];
        #pragma unroll
        for (int p = 0; p < 8; p++) {
            unsigned int lo, hi;
            asm("mov.b64 {%0, %1}, %2;" : "=r"(lo), "=r"(hi) : "l"(acc[p][pr]));
            float v = __uint_as_float(hf ? hi : lo) + bv[p];
            o[p] = fmaxf(v, 0.f);
        }
        float4 v0 = make_float4(o[0], o[1], o[2], o[3]);
        float4 v1 = make_float4(o[4], o[5], o[6], o[7]);
        *reinterpret_cast<float4*>(out + (size_t)node * EMB + c0)     = v0;
        *reinterpret_cast<float4*>(out + (size_t)node * EMB + c0 + 4) = v1;
    }
}

// ---------------- launch ----------------------------------------------------
extern "C" void kernel_launch(void* const* d_in, const int* in_sizes, int n_in,
                              void* d_out, int out_size) {
    const float* h        = (const float*)d_in[0];   // [E, 128]
    const float* x        = (const float*)d_in[1];   // [N, 128]
    const int*   edge_dst = (const int*)  d_in[2];   // [E] int32
    const float* W        = (const float*)d_in[3];   // [128, 256]
    const float* b        = (const float*)d_in[4];   // [128]
    float*       out      = (float*)d_out;           // [N, 128]

    int E = in_sizes[2];
    int N = in_sizes[1] / EMB;

    cudaFuncSetAttribute(fused_kernel,
                         cudaFuncAttributeMaxDynamicSharedMemorySize,
                         SMEM_BYTES);

    zero_deg_kernel<<<(N + 255) / 256, 256>>>(N);
    hist_rank_kernel<<<(E + 255) / 256, 256>>>(edge_dst, E);
    scan_kernel<<<1, 1024>>>(N);
    scatter_kernel<<<(E + 255) / 256, 256>>>(edge_dst, E);
    fused_kernel<<<(N + BM - 1) / BM, 256, SMEM_BYTES>>>(
        reinterpret_cast<const float4*>(h),
        reinterpret_cast<const float4*>(x),
        W, b, out, N);
}